// round 6
// baseline (speedup 1.0000x reference)
#include <cuda_runtime.h>
#include <cuda_fp16.h>
#include <math.h>

// ---------------------------------------------------------------------------
// AGNN with per-launch dst-CSR; layers are atomic-free warp-per-node gathers.
//   hn = h/||h|| fp16 (64 B/row), norm = max(||h||,eps).
//   layer(d): den = sum_e exp(beta*dot(hn_s,hn_d));
//             acc = sum_e exp(..)*norm[s]*hn[s];
//             h'  = relu(acc/max(den,eps));  renorm -> hn',norm' (or f32 out)
// Max-subtraction skipped (|e|<=|beta|, cosine bounded) — same math.
// ---------------------------------------------------------------------------

#define NN 100000
#define NE 1600000
#define EPSF 1e-12f
#define SCAN_T 1024

__device__ __align__(128) float  g_h2[NN * 32];      // layer-1 output (f32)
__device__ __align__(128) __half g_hnA[NN * 32];
__device__ __align__(128) __half g_hnB[NN * 32];
__device__ __align__(128) float  g_normA[NN];
__device__ __align__(128) float  g_normB[NN];
__device__ __align__(128) int    g_deg[NN];
__device__ __align__(128) int    g_rowoff[NN];
__device__ __align__(128) int    g_cursor[NN];
__device__ __align__(128) int    g_ssrc[NE];

// ---------------------------------------------------------------------------
__global__ void k_zero_i(int* __restrict__ p, int n) {
    int i = blockIdx.x * blockDim.x + threadIdx.x;
    if (i < n) p[i] = 0;
}

__global__ void k_hist(const int* __restrict__ dst, int* __restrict__ deg, int ne) {
    int i = blockIdx.x * blockDim.x + threadIdx.x;
    if (i < ne) atomicAdd(&deg[dst[i]], 1);
}

// Single-block exclusive scan of deg -> rowoff (+ copy to cursor).
__global__ __launch_bounds__(SCAN_T) void k_scan(
    const int* __restrict__ deg, int* __restrict__ rowoff,
    int* __restrict__ cursor, int n)
{
    __shared__ int s[SCAN_T];
    int t = threadIdx.x;
    int chunk = (n + SCAN_T - 1) / SCAN_T;
    int begin = t * chunk;
    int end   = min(begin + chunk, n);

    int sum = 0;
    for (int i = begin; i < end; i++) sum += deg[i];
    s[t] = sum;
    __syncthreads();

    for (int off = 1; off < SCAN_T; off <<= 1) {
        int v = (t >= off) ? s[t - off] : 0;
        __syncthreads();
        if (t >= off) s[t] += v;
        __syncthreads();
    }
    int run = (t == 0) ? 0 : s[t - 1];
    for (int i = begin; i < end; i++) {
        rowoff[i] = run;
        cursor[i] = run;
        run += deg[i];
    }
}

__global__ void k_scatter_idx(const int* __restrict__ src, const int* __restrict__ dst,
                              int* __restrict__ cursor, int* __restrict__ ssrc, int ne) {
    int i = blockIdx.x * blockDim.x + threadIdx.x;
    if (i < ne) {
        int pos = atomicAdd(&cursor[dst[i]], 1);
        ssrc[pos] = src[i];
    }
}

// ---------------------------------------------------------------------------
// GEMM1: h1 = relu(F @ w1^T + b1); write hn fp16 + norm.
__global__ __launch_bounds__(256) void k_gemm1(
    const float* __restrict__ feat, const float* __restrict__ w1,
    const float* __restrict__ b1, __half* __restrict__ hn,
    float* __restrict__ normv, int n)
{
    __shared__ float w1t[128 * 32];
    __shared__ float b1s[32];
    for (int i = threadIdx.x; i < 4096; i += 256) {
        int j = i >> 7, k = i & 127;
        w1t[k * 32 + j] = w1[i];
    }
    if (threadIdx.x < 32) b1s[threadIdx.x] = b1[threadIdx.x];
    __syncthreads();

    int node = blockIdx.x * 256 + threadIdx.x;
    if (node >= n) return;

    float acc[32];
    #pragma unroll
    for (int j = 0; j < 32; j++) acc[j] = b1s[j];

    const float4* f4 = reinterpret_cast<const float4*>(feat + (size_t)node * 128);
    #pragma unroll 4
    for (int k4 = 0; k4 < 32; k4++) {
        float4 f = f4[k4];
        float fv[4] = {f.x, f.y, f.z, f.w};
        #pragma unroll
        for (int c = 0; c < 4; c++) {
            const float4* w4 = reinterpret_cast<const float4*>(&w1t[(k4 * 4 + c) * 32]);
            #pragma unroll
            for (int j4 = 0; j4 < 8; j4++) {
                float4 w = w4[j4];
                acc[j4 * 4 + 0] += fv[c] * w.x;
                acc[j4 * 4 + 1] += fv[c] * w.y;
                acc[j4 * 4 + 2] += fv[c] * w.z;
                acc[j4 * 4 + 3] += fv[c] * w.w;
            }
        }
    }

    float ss = 0.f;
    #pragma unroll
    for (int j = 0; j < 32; j++) {
        float v = fmaxf(acc[j], 0.f);
        acc[j] = v;
        ss += v * v;
    }
    float nv = fmaxf(sqrtf(ss), EPSF);
    float rinv = 1.0f / nv;
    normv[node] = nv;

    __half2 hp[16];
    #pragma unroll
    for (int j = 0; j < 16; j++)
        hp[j] = __floats2half2_rn(acc[2 * j] * rinv, acc[2 * j + 1] * rinv);
    uint4* o = reinterpret_cast<uint4*>(hn + (size_t)node * 32);
    const uint4* s4 = reinterpret_cast<const uint4*>(hp);
    #pragma unroll
    for (int j = 0; j < 4; j++) o[j] = s4[j];
}

// ---------------------------------------------------------------------------
// AGNN layer, warp per dst node, 4 edge-subgroups of 8 lanes. No atomics.
// WRITE_F32 = 0: write hn fp16 + norm (mid layer);  = 1: write h f32 (last).
template <int WRITE_F32>
__global__ __launch_bounds__(256) void k_layer(
    const int* __restrict__ rowoff, const int* __restrict__ deg,
    const int* __restrict__ ssrc,
    const __half* __restrict__ hn_in, const float* __restrict__ norm_in,
    const float* __restrict__ betas, int layer,
    __half* __restrict__ hn_out, float* __restrict__ norm_out,
    float* __restrict__ hf_out, int n)
{
    int warp = (blockIdx.x * 256 + threadIdx.x) >> 5;
    int lane = threadIdx.x & 31;
    int sub  = lane >> 3;          // edge subgroup 0..3
    int l8   = lane & 7;           // float4-chunk id within row
    if (warp >= n) return;
    int d = warp;

    unsigned smask = 0xFFu << (sub * 8);

    // hn[d] chunk l8 (replicated across subgroups; broadcast from L1)
    uint2 pb = *(reinterpret_cast<const uint2*>(hn_in + (size_t)d * 32) + l8);
    float2 b0 = __half22float2(*reinterpret_cast<const __half2*>(&pb.x));
    float2 b1 = __half22float2(*reinterpret_cast<const __half2*>(&pb.y));

    float beta = __ldg(&betas[layer]);
    int start = rowoff[d];
    int dg    = deg[d];

    float4 acc = make_float4(0.f, 0.f, 0.f, 0.f);
    float  den = 0.f;

    for (int i = sub; i < dg; i += 4) {
        int s = ssrc[start + i];
        uint2 pa = *(reinterpret_cast<const uint2*>(hn_in + (size_t)s * 32) + l8);
        float2 a0 = __half22float2(*reinterpret_cast<const __half2*>(&pa.x));
        float2 a1 = __half22float2(*reinterpret_cast<const __half2*>(&pa.y));

        float p = a0.x * b0.x + a0.y * b0.y + a1.x * b1.x + a1.y * b1.y;
        p += __shfl_xor_sync(smask, p, 1);
        p += __shfl_xor_sync(smask, p, 2);
        p += __shfl_xor_sync(smask, p, 4);

        float v = __expf(beta * p);
        float w = v * __ldg(&norm_in[s]);
        den   += v;
        acc.x += w * a0.x;  acc.y += w * a0.y;
        acc.z += w * a1.x;  acc.w += w * a1.y;
    }

    // combine subgroups (same l8, different sub): xor 8, 16
    acc.x += __shfl_xor_sync(0xFFFFFFFFu, acc.x, 8);
    acc.y += __shfl_xor_sync(0xFFFFFFFFu, acc.y, 8);
    acc.z += __shfl_xor_sync(0xFFFFFFFFu, acc.z, 8);
    acc.w += __shfl_xor_sync(0xFFFFFFFFu, acc.w, 8);
    den   += __shfl_xor_sync(0xFFFFFFFFu, den,   8);
    acc.x += __shfl_xor_sync(0xFFFFFFFFu, acc.x, 16);
    acc.y += __shfl_xor_sync(0xFFFFFFFFu, acc.y, 16);
    acc.z += __shfl_xor_sync(0xFFFFFFFFu, acc.z, 16);
    acc.w += __shfl_xor_sync(0xFFFFFFFFu, acc.w, 16);
    den   += __shfl_xor_sync(0xFFFFFFFFu, den,   16);

    float inv = 1.0f / fmaxf(den, EPSF);
    float4 h;
    h.x = fmaxf(acc.x * inv, 0.f);
    h.y = fmaxf(acc.y * inv, 0.f);
    h.z = fmaxf(acc.z * inv, 0.f);
    h.w = fmaxf(acc.w * inv, 0.f);

    if (WRITE_F32) {
        if (sub == 0)
            *(reinterpret_cast<float4*>(hf_out + (size_t)d * 32) + l8) = h;
    } else {
        float ss = h.x * h.x + h.y * h.y + h.z * h.z + h.w * h.w;
        ss += __shfl_xor_sync(0xFFFFFFFFu, ss, 1);
        ss += __shfl_xor_sync(0xFFFFFFFFu, ss, 2);
        ss += __shfl_xor_sync(0xFFFFFFFFu, ss, 4);
        float nv = fmaxf(sqrtf(ss), EPSF);
        float rinv = 1.0f / nv;
        if (lane == 0) norm_out[d] = nv;
        if (sub == 0) {
            __half2 h0 = __floats2half2_rn(h.x * rinv, h.y * rinv);
            __half2 h1 = __floats2half2_rn(h.z * rinv, h.w * rinv);
            uint2 pk;
            pk.x = *reinterpret_cast<unsigned*>(&h0);
            pk.y = *reinterpret_cast<unsigned*>(&h1);
            *(reinterpret_cast<uint2*>(hn_out + (size_t)d * 32) + l8) = pk;
        }
    }
}

// ---------------------------------------------------------------------------
// Head: out = log_softmax(relu(h) @ w2^T + b2). Thread-per-node.
__global__ __launch_bounds__(128) void k_final(
    const float* __restrict__ hin, const float* __restrict__ w2,
    const float* __restrict__ b2, float* __restrict__ out, int n)
{
    __shared__ float w2t[32 * 64];
    __shared__ float b2s[64];
    for (int i = threadIdx.x; i < 2048; i += 128) {
        int j = i >> 5, k = i & 31;
        w2t[k * 64 + j] = w2[i];
    }
    for (int i = threadIdx.x; i < 64; i += 128) b2s[i] = b2[i];
    __syncthreads();

    int node = blockIdx.x * 128 + threadIdx.x;
    if (node >= n) return;

    float acc[64];
    #pragma unroll
    for (int j = 0; j < 64; j++) acc[j] = b2s[j];

    const float4* h4 = reinterpret_cast<const float4*>(hin + (size_t)node * 32);
    #pragma unroll
    for (int k4 = 0; k4 < 8; k4++) {
        float4 hv = h4[k4];
        float hh[4] = {hv.x, hv.y, hv.z, hv.w};   // already relu'd
        #pragma unroll
        for (int c = 0; c < 4; c++) {
            const float4* w4 = reinterpret_cast<const float4*>(&w2t[(k4 * 4 + c) * 64]);
            float f = hh[c];
            #pragma unroll
            for (int j4 = 0; j4 < 16; j4++) {
                float4 w = w4[j4];
                acc[j4 * 4 + 0] += f * w.x;
                acc[j4 * 4 + 1] += f * w.y;
                acc[j4 * 4 + 2] += f * w.z;
                acc[j4 * 4 + 3] += f * w.w;
            }
        }
    }

    float mx = acc[0];
    #pragma unroll
    for (int j = 1; j < 64; j++) mx = fmaxf(mx, acc[j]);
    float sum = 0.f;
    #pragma unroll
    for (int j = 0; j < 64; j++) sum += __expf(acc[j] - mx);
    float lse = mx + __logf(sum);

    float4* o4 = reinterpret_cast<float4*>(out + (size_t)node * 64);
    #pragma unroll
    for (int j4 = 0; j4 < 16; j4++)
        o4[j4] = make_float4(acc[j4 * 4] - lse, acc[j4 * 4 + 1] - lse,
                             acc[j4 * 4 + 2] - lse, acc[j4 * 4 + 3] - lse);
}

// ---------------------------------------------------------------------------
extern "C" void kernel_launch(void* const* d_in, const int* in_sizes, int n_in,
                              void* d_out, int out_size)
{
    const float* feat  = (const float*)d_in[0];
    const int*   src   = (const int*)d_in[1];
    const int*   dst   = (const int*)d_in[2];
    const float* w1    = (const float*)d_in[3];
    const float* b1    = (const float*)d_in[4];
    const float* betas = (const float*)d_in[5];
    const float* w2    = (const float*)d_in[6];
    const float* b2    = (const float*)d_in[7];
    float*       out   = (float*)d_out;

    const int n  = in_sizes[0] / 128;   // 100000
    const int ne = in_sizes[1];         // 1600000

    float  *h2, *normA, *normB;
    __half *hnA, *hnB;
    int *deg, *rowoff, *cursor, *ssrc;
    cudaGetSymbolAddress((void**)&h2,     g_h2);
    cudaGetSymbolAddress((void**)&hnA,    g_hnA);
    cudaGetSymbolAddress((void**)&hnB,    g_hnB);
    cudaGetSymbolAddress((void**)&normA,  g_normA);
    cudaGetSymbolAddress((void**)&normB,  g_normB);
    cudaGetSymbolAddress((void**)&deg,    g_deg);
    cudaGetSymbolAddress((void**)&rowoff, g_rowoff);
    cudaGetSymbolAddress((void**)&cursor, g_cursor);
    cudaGetSymbolAddress((void**)&ssrc,   g_ssrc);

    const int TB = 256;
    dim3 gN((n + TB - 1) / TB);
    dim3 gE((ne + TB - 1) / TB);
    dim3 gW((n * 32 + TB - 1) / TB);   // warp-per-node kernels

    // CSR build (per launch; graph-capturable, atomic cursor order is fp-benign)
    k_zero_i<<<gN, TB>>>(deg, n);
    k_hist<<<gE, TB>>>(dst, deg, ne);
    k_scan<<<1, SCAN_T>>>(deg, rowoff, cursor, n);
    k_scatter_idx<<<gE, TB>>>(src, dst, cursor, ssrc, ne);

    // K1: hn0/norm0
    k_gemm1<<<gN, TB>>>(feat, w1, b1, hnA, normA, n);

    // Layer 0: hnA -> hnB (fp16) ; Layer 1: hnB -> h2 (f32)
    k_layer<0><<<gW, TB>>>(rowoff, deg, ssrc, hnA, normA, betas, 0,
                           hnB, normB, (float*)nullptr, n);
    k_layer<1><<<gW, TB>>>(rowoff, deg, ssrc, hnB, normB, betas, 1,
                           (__half*)nullptr, (float*)nullptr, h2, n);

    // Head
    k_final<<<(n + 127) / 128, 128>>>(h2, w2, b2, out, n);
}

// round 7
// speedup vs baseline: 1.0558x; 1.0558x over previous
#include <cuda_runtime.h>
#include <cuda_fp16.h>
#include <math.h>

// ---------------------------------------------------------------------------
// AGNN, dst-sorted edge list + flat segmented-reduction layer kernels.
//   hn = h/||h|| fp16 (64 B/row), norm = ||h||.
//   CSR build per launch: deg hist -> scan -> cursor scatter of int2{src,dst}.
//   Layer (flat, 8 lanes/edge over sorted edges):
//     v = exp(beta*dot(hn_s,hn_d)); contributions warp-segment-reduced by d,
//     tail slot REDs denom[d] and agg[d] (vec4).
//   Then h' = relu(agg/denom) (norm_mid / fused into final).
// Max-subtraction skipped (|e| <= |beta|, cosine bounded) — same math.
// ---------------------------------------------------------------------------

#define NN 100000
#define NE 1600000
#define EPSF 1e-12f
#define SCAN_T 1024
#define FULLM 0xFFFFFFFFu

__device__ __align__(128) float  g_agg[NN * 32];
__device__ __align__(128) __half g_hnA[NN * 32];
__device__ __align__(128) __half g_hnB[NN * 32];
__device__ __align__(128) float  g_norm[NN];
__device__ __align__(128) float  g_denom[NN];
__device__ __align__(128) int    g_deg[NN];
__device__ __align__(128) int    g_cursor[NN];
__device__ __align__(128) int2   g_sedge[NE];

// ---------------------------------------------------------------------------
__global__ void k_zero_i(int* __restrict__ p, int n) {
    int i = blockIdx.x * blockDim.x + threadIdx.x;
    if (i < n) p[i] = 0;
}

__global__ void k_zero_layer(float4* __restrict__ agg, float4* __restrict__ denom,
                             int n_agg4, int n_den4) {
    int i = blockIdx.x * blockDim.x + threadIdx.x;
    if (i < n_agg4) agg[i] = make_float4(0.f, 0.f, 0.f, 0.f);
    if (i < n_den4) denom[i] = make_float4(0.f, 0.f, 0.f, 0.f);
}

__global__ void k_hist(const int* __restrict__ dst, int* __restrict__ deg, int ne) {
    int i = blockIdx.x * blockDim.x + threadIdx.x;
    if (i < ne) atomicAdd(&deg[dst[i]], 1);
}

// Single-block exclusive scan of deg -> cursor (start offsets).
__global__ __launch_bounds__(SCAN_T) void k_scan(
    const int* __restrict__ deg, int* __restrict__ cursor, int n)
{
    __shared__ int s[SCAN_T];
    int t = threadIdx.x;
    int chunk = (n + SCAN_T - 1) / SCAN_T;
    int begin = t * chunk;
    int end   = min(begin + chunk, n);

    int sum = 0;
    for (int i = begin; i < end; i++) sum += deg[i];
    s[t] = sum;
    __syncthreads();

    for (int off = 1; off < SCAN_T; off <<= 1) {
        int v = (t >= off) ? s[t - off] : 0;
        __syncthreads();
        if (t >= off) s[t] += v;
        __syncthreads();
    }
    int run = (t == 0) ? 0 : s[t - 1];
    for (int i = begin; i < end; i++) {
        cursor[i] = run;
        run += deg[i];
    }
}

__global__ void k_scatter_idx(const int* __restrict__ src, const int* __restrict__ dst,
                              int* __restrict__ cursor, int2* __restrict__ sedge, int ne) {
    int i = blockIdx.x * blockDim.x + threadIdx.x;
    if (i < ne) {
        int d = dst[i];
        int pos = atomicAdd(&cursor[d], 1);
        sedge[pos] = make_int2(src[i], d);
    }
}

// ---------------------------------------------------------------------------
// GEMM1: h1 = relu(F @ w1^T + b1); write hn fp16 + norm.
__global__ __launch_bounds__(256) void k_gemm1(
    const float* __restrict__ feat, const float* __restrict__ w1,
    const float* __restrict__ b1, __half* __restrict__ hn,
    float* __restrict__ normv, int n)
{
    __shared__ float w1t[128 * 32];
    __shared__ float b1s[32];
    for (int i = threadIdx.x; i < 4096; i += 256) {
        int j = i >> 7, k = i & 127;
        w1t[k * 32 + j] = w1[i];
    }
    if (threadIdx.x < 32) b1s[threadIdx.x] = b1[threadIdx.x];
    __syncthreads();

    int node = blockIdx.x * 256 + threadIdx.x;
    if (node >= n) return;

    float acc[32];
    #pragma unroll
    for (int j = 0; j < 32; j++) acc[j] = b1s[j];

    const float4* f4 = reinterpret_cast<const float4*>(feat + (size_t)node * 128);
    #pragma unroll 4
    for (int k4 = 0; k4 < 32; k4++) {
        float4 f = f4[k4];
        float fv[4] = {f.x, f.y, f.z, f.w};
        #pragma unroll
        for (int c = 0; c < 4; c++) {
            const float4* w4 = reinterpret_cast<const float4*>(&w1t[(k4 * 4 + c) * 32]);
            #pragma unroll
            for (int j4 = 0; j4 < 8; j4++) {
                float4 w = w4[j4];
                acc[j4 * 4 + 0] += fv[c] * w.x;
                acc[j4 * 4 + 1] += fv[c] * w.y;
                acc[j4 * 4 + 2] += fv[c] * w.z;
                acc[j4 * 4 + 3] += fv[c] * w.w;
            }
        }
    }

    float ss = 0.f;
    #pragma unroll
    for (int j = 0; j < 32; j++) {
        float v = fmaxf(acc[j], 0.f);
        acc[j] = v;
        ss += v * v;
    }
    float nv = fmaxf(sqrtf(ss), EPSF);
    float rinv = 1.0f / nv;
    normv[node] = nv;

    __half2 hp[16];
    #pragma unroll
    for (int j = 0; j < 16; j++)
        hp[j] = __floats2half2_rn(acc[2 * j] * rinv, acc[2 * j + 1] * rinv);
    uint4* o = reinterpret_cast<uint4*>(hn + (size_t)node * 32);
    const uint4* s4 = reinterpret_cast<const uint4*>(hp);
    #pragma unroll
    for (int j = 0; j < 4; j++) o[j] = s4[j];
}

// ---------------------------------------------------------------------------
// Flat layer kernel over dst-SORTED edges, 8 lanes/edge (4 edge slots/warp).
// Warp-level segmented reduction by d; tail slot REDs denom + agg.
__global__ __launch_bounds__(256) void k_layer_sorted(
    const int2* __restrict__ sedge,
    const __half* __restrict__ hn, const float* __restrict__ normv,
    const float* __restrict__ betas, int layer,
    float* __restrict__ denom, float* __restrict__ agg, int ne)
{
    int gid  = blockIdx.x * 256 + threadIdx.x;
    int e    = gid >> 3;
    int lane = threadIdx.x & 31;
    int se   = lane >> 3;          // edge slot 0..3
    int l8   = lane & 7;           // float4-chunk id

    bool valid = (e < ne);
    int2 ed = valid ? sedge[e] : make_int2(0, -1);
    int s = ed.x, d = ed.y;

    unsigned smask = 0xFFu << (se * 8);

    float den = 0.f;
    float4 acc = make_float4(0.f, 0.f, 0.f, 0.f);
    float2 a0 = make_float2(0.f, 0.f), a1 = make_float2(0.f, 0.f);

    if (valid) {
        uint2 pa = *(reinterpret_cast<const uint2*>(hn + (size_t)s * 32) + l8);
        uint2 pb = *(reinterpret_cast<const uint2*>(hn + (size_t)d * 32) + l8);
        a0 = __half22float2(*reinterpret_cast<const __half2*>(&pa.x));
        a1 = __half22float2(*reinterpret_cast<const __half2*>(&pa.y));
        float2 b0 = __half22float2(*reinterpret_cast<const __half2*>(&pb.x));
        float2 b1 = __half22float2(*reinterpret_cast<const __half2*>(&pb.y));
        float p = a0.x * b0.x + a0.y * b0.y + a1.x * b1.x + a1.y * b1.y;
        p += __shfl_xor_sync(FULLM, p, 1);
        p += __shfl_xor_sync(FULLM, p, 2);
        p += __shfl_xor_sync(FULLM, p, 4);
        float v = __expf(__ldg(&betas[layer]) * p);
        float w = v * __ldg(&normv[s]);
        den = v;
        acc = make_float4(w * a0.x, w * a0.y, w * a1.x, w * a1.y);
    } else {
        // keep shuffles convergent; zero contribution
        float p = 0.f;
        p += __shfl_xor_sync(FULLM, p, 1);
        p += __shfl_xor_sync(FULLM, p, 2);
        p += __shfl_xor_sync(FULLM, p, 4);
    }

    // ---- segmented inclusive scan over the 4 edge slots (sorted d) ----
    int d_up1 = __shfl_up_sync(FULLM, d, 8);
    int d_up2 = __shfl_up_sync(FULLM, d, 16);
    bool same1 = (se >= 1) && (d == d_up1);
    bool same2 = (se >= 2) && (d == d_up2);

    float t;
    t = __shfl_up_sync(FULLM, den,   8); if (same1) den   += t;
    t = __shfl_up_sync(FULLM, acc.x, 8); if (same1) acc.x += t;
    t = __shfl_up_sync(FULLM, acc.y, 8); if (same1) acc.y += t;
    t = __shfl_up_sync(FULLM, acc.z, 8); if (same1) acc.z += t;
    t = __shfl_up_sync(FULLM, acc.w, 8); if (same1) acc.w += t;

    t = __shfl_up_sync(FULLM, den,   16); if (same2) den   += t;
    t = __shfl_up_sync(FULLM, acc.x, 16); if (same2) acc.x += t;
    t = __shfl_up_sync(FULLM, acc.y, 16); if (same2) acc.y += t;
    t = __shfl_up_sync(FULLM, acc.z, 16); if (same2) acc.z += t;
    t = __shfl_up_sync(FULLM, acc.w, 16); if (same2) acc.w += t;

    int d_dn1 = __shfl_down_sync(FULLM, d, 8);
    bool tail = (se == 3) || (d != d_dn1);

    if (valid && tail) {
        if (l8 == 0) atomicAdd(&denom[d], den);
        atomicAdd(reinterpret_cast<float4*>(agg + (size_t)d * 32) + l8, acc);
    }
}

// ---------------------------------------------------------------------------
// Layer-0 node pass, 8 lanes/node: h = relu(agg/denom); write hn fp16 + norm.
__global__ __launch_bounds__(256) void k_norm_mid(
    const float* __restrict__ agg, const float* __restrict__ denom,
    __half* __restrict__ hn, float* __restrict__ normv, int n)
{
    int gid  = blockIdx.x * 256 + threadIdx.x;
    int node = gid >> 3;
    int lane = threadIdx.x & 7;
    if (node >= n) return;
    unsigned mask = __activemask();

    float inv = 1.0f / fmaxf(denom[node], EPSF);
    float4 v = *(reinterpret_cast<const float4*>(agg + (size_t)node * 32) + lane);
    v.x = fmaxf(v.x * inv, 0.f); v.y = fmaxf(v.y * inv, 0.f);
    v.z = fmaxf(v.z * inv, 0.f); v.w = fmaxf(v.w * inv, 0.f);

    float ss = v.x * v.x + v.y * v.y + v.z * v.z + v.w * v.w;
    ss += __shfl_xor_sync(mask, ss, 1);
    ss += __shfl_xor_sync(mask, ss, 2);
    ss += __shfl_xor_sync(mask, ss, 4);

    float nv = fmaxf(sqrtf(ss), EPSF);
    float rinv = 1.0f / nv;
    if (lane == 0) normv[node] = nv;

    __half2 h0 = __floats2half2_rn(v.x * rinv, v.y * rinv);
    __half2 h1 = __floats2half2_rn(v.z * rinv, v.w * rinv);
    uint2 pk;
    pk.x = *reinterpret_cast<unsigned*>(&h0);
    pk.y = *reinterpret_cast<unsigned*>(&h1);
    *(reinterpret_cast<uint2*>(hn + (size_t)node * 32) + lane) = pk;
}

// ---------------------------------------------------------------------------
// Head: h2 = relu(agg/denom); out = log_softmax(h2 @ w2^T + b2).
__global__ __launch_bounds__(128) void k_final(
    const float* __restrict__ agg, const float* __restrict__ denom,
    const float* __restrict__ w2, const float* __restrict__ b2,
    float* __restrict__ out, int n)
{
    __shared__ float w2t[32 * 64];
    __shared__ float b2s[64];
    for (int i = threadIdx.x; i < 2048; i += 128) {
        int j = i >> 5, k = i & 31;
        w2t[k * 64 + j] = w2[i];
    }
    for (int i = threadIdx.x; i < 64; i += 128) b2s[i] = b2[i];
    __syncthreads();

    int node = blockIdx.x * 128 + threadIdx.x;
    if (node >= n) return;

    float inv = 1.0f / fmaxf(denom[node], EPSF);

    float acc[64];
    #pragma unroll
    for (int j = 0; j < 64; j++) acc[j] = b2s[j];

    const float4* h4 = reinterpret_cast<const float4*>(agg + (size_t)node * 32);
    #pragma unroll
    for (int k4 = 0; k4 < 8; k4++) {
        float4 hv = h4[k4];
        float hh[4] = {fmaxf(hv.x * inv, 0.f), fmaxf(hv.y * inv, 0.f),
                       fmaxf(hv.z * inv, 0.f), fmaxf(hv.w * inv, 0.f)};
        #pragma unroll
        for (int c = 0; c < 4; c++) {
            const float4* w4 = reinterpret_cast<const float4*>(&w2t[(k4 * 4 + c) * 64]);
            float f = hh[c];
            #pragma unroll
            for (int j4 = 0; j4 < 16; j4++) {
                float4 w = w4[j4];
                acc[j4 * 4 + 0] += f * w.x;
                acc[j4 * 4 + 1] += f * w.y;
                acc[j4 * 4 + 2] += f * w.z;
                acc[j4 * 4 + 3] += f * w.w;
            }
        }
    }

    float mx = acc[0];
    #pragma unroll
    for (int j = 1; j < 64; j++) mx = fmaxf(mx, acc[j]);
    float sum = 0.f;
    #pragma unroll
    for (int j = 0; j < 64; j++) sum += __expf(acc[j] - mx);
    float lse = mx + __logf(sum);

    float4* o4 = reinterpret_cast<float4*>(out + (size_t)node * 64);
    #pragma unroll
    for (int j4 = 0; j4 < 16; j4++)
        o4[j4] = make_float4(acc[j4 * 4] - lse, acc[j4 * 4 + 1] - lse,
                             acc[j4 * 4 + 2] - lse, acc[j4 * 4 + 3] - lse);
}

// ---------------------------------------------------------------------------
extern "C" void kernel_launch(void* const* d_in, const int* in_sizes, int n_in,
                              void* d_out, int out_size)
{
    const float* feat  = (const float*)d_in[0];
    const int*   src   = (const int*)d_in[1];
    const int*   dst   = (const int*)d_in[2];
    const float* w1    = (const float*)d_in[3];
    const float* b1    = (const float*)d_in[4];
    const float* betas = (const float*)d_in[5];
    const float* w2    = (const float*)d_in[6];
    const float* b2    = (const float*)d_in[7];
    float*       out   = (float*)d_out;

    const int n  = in_sizes[0] / 128;   // 100000
    const int ne = in_sizes[1];         // 1600000

    float *agg, *normv, *denom;
    __half *hnA, *hnB;
    int *deg, *cursor;
    int2 *sedge;
    cudaGetSymbolAddress((void**)&agg,    g_agg);
    cudaGetSymbolAddress((void**)&hnA,    g_hnA);
    cudaGetSymbolAddress((void**)&hnB,    g_hnB);
    cudaGetSymbolAddress((void**)&normv,  g_norm);
    cudaGetSymbolAddress((void**)&denom,  g_denom);
    cudaGetSymbolAddress((void**)&deg,    g_deg);
    cudaGetSymbolAddress((void**)&cursor, g_cursor);
    cudaGetSymbolAddress((void**)&sedge,  g_sedge);

    const int TB = 256;
    const int n_agg4 = n * 32 / 4;
    const int n_den4 = n / 4;
    dim3 gN((n + TB - 1) / TB);
    dim3 gN8(((size_t)n * 8 + TB - 1) / TB);
    dim3 gE((ne + TB - 1) / TB);
    dim3 gE8(((size_t)ne * 8 + TB - 1) / TB);
    dim3 gZ((n_agg4 + TB - 1) / TB);

    // CSR build: deg -> cursor(start offsets) -> dst-sorted int2 edge list
    k_zero_i<<<gN, TB>>>(deg, n);
    k_hist<<<gE, TB>>>(dst, deg, ne);
    k_scan<<<1, SCAN_T>>>(deg, cursor, n);
    k_scatter_idx<<<gE, TB>>>(src, dst, cursor, sedge, ne);

    // K1: hn0/norm0
    k_gemm1<<<gN, TB>>>(feat, w1, b1, hnA, normv, n);

    // ---- layer 0 ----
    k_zero_layer<<<gZ, TB>>>((float4*)agg, (float4*)denom, n_agg4, n_den4);
    k_layer_sorted<<<gE8, TB>>>(sedge, hnA, normv, betas, 0, denom, agg, ne);
    k_norm_mid<<<gN8, TB>>>(agg, denom, hnB, normv, n);

    // ---- layer 1 ----
    k_zero_layer<<<gZ, TB>>>((float4*)agg, (float4*)denom, n_agg4, n_den4);
    k_layer_sorted<<<gE8, TB>>>(sedge, hnB, normv, betas, 1, denom, agg, ne);

    // Head (divide + relu fused)
    k_final<<<(n + 127) / 128, 128>>>(agg, denom, w2, b2, out, n);
}

// round 8
// speedup vs baseline: 1.7805x; 1.6865x over previous
#include <cuda_runtime.h>
#include <cuda_fp16.h>
#include <math.h>

// ---------------------------------------------------------------------------
// AGNN — fp16 normalized-feature edge passes (R5 skeleton), 2 edges per
// 8-lane group in the fused edge kernel for doubled memory-level parallelism.
//   hn[node] = h/||h|| fp16 (64 B/row), norm[node] = max(||h||,eps).
//   edge: v = exp(beta * dot(hn_s,hn_d)); denom[d] += v;
//         agg[d] += (v*norm[s]) * hn[s]   (f32 vec4 RED)
//   node: h' = relu(agg/denom) -> renorm (mid) / fused into head (last).
// Max-subtraction skipped: |e| <= |beta| (cosine bounded) — same math.
// ---------------------------------------------------------------------------

#define NN 100000
#define NE 1600000
#define EPSF 1e-12f
#define FULLM 0xFFFFFFFFu

__device__ __align__(128) float  g_agg[NN * 32];
__device__ __align__(128) __half g_hnA[NN * 32];
__device__ __align__(128) __half g_hnB[NN * 32];
__device__ __align__(128) float  g_norm[NN];
__device__ __align__(128) float  g_denom[NN];

// ---------------------------------------------------------------------------
__global__ void k_zero_layer(float4* __restrict__ agg, float4* __restrict__ denom,
                             int n_agg4, int n_den4) {
    int i = blockIdx.x * blockDim.x + threadIdx.x;
    if (i < n_agg4) agg[i] = make_float4(0.f, 0.f, 0.f, 0.f);
    if (i < n_den4) denom[i] = make_float4(0.f, 0.f, 0.f, 0.f);
}

// ---------------------------------------------------------------------------
// GEMM1: h1 = relu(F @ w1^T + b1); write hn fp16 + norm.
__global__ __launch_bounds__(256) void k_gemm1(
    const float* __restrict__ feat, const float* __restrict__ w1,
    const float* __restrict__ b1, __half* __restrict__ hn,
    float* __restrict__ normv, int n)
{
    __shared__ float w1t[128 * 32];
    __shared__ float b1s[32];
    for (int i = threadIdx.x; i < 4096; i += 256) {
        int j = i >> 7, k = i & 127;
        w1t[k * 32 + j] = w1[i];
    }
    if (threadIdx.x < 32) b1s[threadIdx.x] = b1[threadIdx.x];
    __syncthreads();

    int node = blockIdx.x * 256 + threadIdx.x;
    if (node >= n) return;

    float acc[32];
    #pragma unroll
    for (int j = 0; j < 32; j++) acc[j] = b1s[j];

    const float4* f4 = reinterpret_cast<const float4*>(feat + (size_t)node * 128);
    #pragma unroll 4
    for (int k4 = 0; k4 < 32; k4++) {
        float4 f = f4[k4];
        float fv[4] = {f.x, f.y, f.z, f.w};
        #pragma unroll
        for (int c = 0; c < 4; c++) {
            const float4* w4 = reinterpret_cast<const float4*>(&w1t[(k4 * 4 + c) * 32]);
            #pragma unroll
            for (int j4 = 0; j4 < 8; j4++) {
                float4 w = w4[j4];
                acc[j4 * 4 + 0] += fv[c] * w.x;
                acc[j4 * 4 + 1] += fv[c] * w.y;
                acc[j4 * 4 + 2] += fv[c] * w.z;
                acc[j4 * 4 + 3] += fv[c] * w.w;
            }
        }
    }

    float ss = 0.f;
    #pragma unroll
    for (int j = 0; j < 32; j++) {
        float v = fmaxf(acc[j], 0.f);
        acc[j] = v;
        ss += v * v;
    }
    float nv = fmaxf(sqrtf(ss), EPSF);
    float rinv = 1.0f / nv;
    normv[node] = nv;

    __half2 hp[16];
    #pragma unroll
    for (int j = 0; j < 16; j++)
        hp[j] = __floats2half2_rn(acc[2 * j] * rinv, acc[2 * j + 1] * rinv);
    uint4* o = reinterpret_cast<uint4*>(hn + (size_t)node * 32);
    const uint4* s4 = reinterpret_cast<const uint4*>(hp);
    #pragma unroll
    for (int j = 0; j < 4; j++) o[j] = s4[j];
}

// ---------------------------------------------------------------------------
// Fused edge pass: 8 lanes/edge-pair — each group handles edges 2g, 2g+1.
// Doubled independent gather chains per warp for MLP.
__global__ __launch_bounds__(256) void k_edge_fused(
    const int* __restrict__ src, const int* __restrict__ dst,
    const __half* __restrict__ hn, const float* __restrict__ normv,
    const float* __restrict__ betas, int layer,
    float* __restrict__ denom, float* __restrict__ agg, int ne)
{
    int gid   = blockIdx.x * 256 + threadIdx.x;
    int group = gid >> 3;
    int lane  = threadIdx.x & 7;
    int e0    = group * 2;
    int e1    = e0 + 1;
    if (e0 >= ne) return;
    bool has1 = (e1 < ne);
    unsigned mask = __activemask();

    int s0 = src[e0], d0 = dst[e0];
    int s1 = has1 ? src[e1] : s0;
    int d1 = has1 ? dst[e1] : d0;

    // 4 independent gathers in flight
    uint2 pa0 = *(reinterpret_cast<const uint2*>(hn + (size_t)s0 * 32) + lane);
    uint2 pb0 = *(reinterpret_cast<const uint2*>(hn + (size_t)d0 * 32) + lane);
    uint2 pa1 = *(reinterpret_cast<const uint2*>(hn + (size_t)s1 * 32) + lane);
    uint2 pb1 = *(reinterpret_cast<const uint2*>(hn + (size_t)d1 * 32) + lane);

    float2 a00 = __half22float2(*reinterpret_cast<const __half2*>(&pa0.x));
    float2 a01 = __half22float2(*reinterpret_cast<const __half2*>(&pa0.y));
    float2 b00 = __half22float2(*reinterpret_cast<const __half2*>(&pb0.x));
    float2 b01 = __half22float2(*reinterpret_cast<const __half2*>(&pb0.y));
    float2 a10 = __half22float2(*reinterpret_cast<const __half2*>(&pa1.x));
    float2 a11 = __half22float2(*reinterpret_cast<const __half2*>(&pa1.y));
    float2 b10 = __half22float2(*reinterpret_cast<const __half2*>(&pb1.x));
    float2 b11 = __half22float2(*reinterpret_cast<const __half2*>(&pb1.y));

    float p0 = a00.x * b00.x + a00.y * b00.y + a01.x * b01.x + a01.y * b01.y;
    float p1 = a10.x * b10.x + a10.y * b10.y + a11.x * b11.x + a11.y * b11.y;
    p0 += __shfl_xor_sync(mask, p0, 1);
    p1 += __shfl_xor_sync(mask, p1, 1);
    p0 += __shfl_xor_sync(mask, p0, 2);
    p1 += __shfl_xor_sync(mask, p1, 2);
    p0 += __shfl_xor_sync(mask, p0, 4);
    p1 += __shfl_xor_sync(mask, p1, 4);

    float beta = __ldg(&betas[layer]);
    float v0 = __expf(beta * p0);
    float v1 = __expf(beta * p1);
    float w0 = v0 * __ldg(&normv[s0]);
    float w1 = v1 * __ldg(&normv[s1]);

    if (lane == 0) atomicAdd(&denom[d0], v0);
    atomicAdd(reinterpret_cast<float4*>(agg + (size_t)d0 * 32) + lane,
              make_float4(w0 * a00.x, w0 * a00.y, w0 * a01.x, w0 * a01.y));

    if (has1) {
        if (lane == 0) atomicAdd(&denom[d1], v1);
        atomicAdd(reinterpret_cast<float4*>(agg + (size_t)d1 * 32) + lane,
                  make_float4(w1 * a10.x, w1 * a10.y, w1 * a11.x, w1 * a11.y));
    }
}

// ---------------------------------------------------------------------------
// Layer-0 node pass, 8 lanes/node: h = relu(agg/denom); write hn fp16 + norm.
__global__ __launch_bounds__(256) void k_norm_mid(
    const float* __restrict__ agg, const float* __restrict__ denom,
    __half* __restrict__ hn, float* __restrict__ normv, int n)
{
    int gid  = blockIdx.x * 256 + threadIdx.x;
    int node = gid >> 3;
    int lane = threadIdx.x & 7;
    if (node >= n) return;
    unsigned mask = __activemask();

    float inv = 1.0f / fmaxf(denom[node], EPSF);
    float4 v = *(reinterpret_cast<const float4*>(agg + (size_t)node * 32) + lane);
    v.x = fmaxf(v.x * inv, 0.f); v.y = fmaxf(v.y * inv, 0.f);
    v.z = fmaxf(v.z * inv, 0.f); v.w = fmaxf(v.w * inv, 0.f);

    float ss = v.x * v.x + v.y * v.y + v.z * v.z + v.w * v.w;
    ss += __shfl_xor_sync(mask, ss, 1);
    ss += __shfl_xor_sync(mask, ss, 2);
    ss += __shfl_xor_sync(mask, ss, 4);

    float nv = fmaxf(sqrtf(ss), EPSF);
    float rinv = 1.0f / nv;
    if (lane == 0) normv[node] = nv;

    __half2 h0 = __floats2half2_rn(v.x * rinv, v.y * rinv);
    __half2 h1 = __floats2half2_rn(v.z * rinv, v.w * rinv);
    uint2 pk;
    pk.x = *reinterpret_cast<unsigned*>(&h0);
    pk.y = *reinterpret_cast<unsigned*>(&h1);
    *(reinterpret_cast<uint2*>(hn + (size_t)node * 32) + lane) = pk;
}

// ---------------------------------------------------------------------------
// Head: h2 = relu(agg/denom); out = log_softmax(h2 @ w2^T + b2).
__global__ __launch_bounds__(128) void k_final(
    const float* __restrict__ agg, const float* __restrict__ denom,
    const float* __restrict__ w2, const float* __restrict__ b2,
    float* __restrict__ out, int n)
{
    __shared__ float w2t[32 * 64];
    __shared__ float b2s[64];
    for (int i = threadIdx.x; i < 2048; i += 128) {
        int j = i >> 5, k = i & 31;
        w2t[k * 64 + j] = w2[i];
    }
    for (int i = threadIdx.x; i < 64; i += 128) b2s[i] = b2[i];
    __syncthreads();

    int node = blockIdx.x * 128 + threadIdx.x;
    if (node >= n) return;

    float inv = 1.0f / fmaxf(denom[node], EPSF);

    float acc[64];
    #pragma unroll
    for (int j = 0; j < 64; j++) acc[j] = b2s[j];

    const float4* h4 = reinterpret_cast<const float4*>(agg + (size_t)node * 32);
    #pragma unroll
    for (int k4 = 0; k4 < 8; k4++) {
        float4 hv = h4[k4];
        float hh[4] = {fmaxf(hv.x * inv, 0.f), fmaxf(hv.y * inv, 0.f),
                       fmaxf(hv.z * inv, 0.f), fmaxf(hv.w * inv, 0.f)};
        #pragma unroll
        for (int c = 0; c < 4; c++) {
            const float4* w4 = reinterpret_cast<const float4*>(&w2t[(k4 * 4 + c) * 64]);
            float f = hh[c];
            #pragma unroll
            for (int j4 = 0; j4 < 16; j4++) {
                float4 w = w4[j4];
                acc[j4 * 4 + 0] += f * w.x;
                acc[j4 * 4 + 1] += f * w.y;
                acc[j4 * 4 + 2] += f * w.z;
                acc[j4 * 4 + 3] += f * w.w;
            }
        }
    }

    float mx = acc[0];
    #pragma unroll
    for (int j = 1; j < 64; j++) mx = fmaxf(mx, acc[j]);
    float sum = 0.f;
    #pragma unroll
    for (int j = 0; j < 64; j++) sum += __expf(acc[j] - mx);
    float lse = mx + __logf(sum);

    float4* o4 = reinterpret_cast<float4*>(out + (size_t)node * 64);
    #pragma unroll
    for (int j4 = 0; j4 < 16; j4++)
        o4[j4] = make_float4(acc[j4 * 4] - lse, acc[j4 * 4 + 1] - lse,
                             acc[j4 * 4 + 2] - lse, acc[j4 * 4 + 3] - lse);
}

// ---------------------------------------------------------------------------
extern "C" void kernel_launch(void* const* d_in, const int* in_sizes, int n_in,
                              void* d_out, int out_size)
{
    const float* feat  = (const float*)d_in[0];
    const int*   src   = (const int*)d_in[1];
    const int*   dst   = (const int*)d_in[2];
    const float* w1    = (const float*)d_in[3];
    const float* b1    = (const float*)d_in[4];
    const float* betas = (const float*)d_in[5];
    const float* w2    = (const float*)d_in[6];
    const float* b2    = (const float*)d_in[7];
    float*       out   = (float*)d_out;

    const int n  = in_sizes[0] / 128;   // 100000
    const int ne = in_sizes[1];         // 1600000

    float *agg, *normv, *denom;
    __half *hnA, *hnB;
    cudaGetSymbolAddress((void**)&agg,   g_agg);
    cudaGetSymbolAddress((void**)&hnA,   g_hnA);
    cudaGetSymbolAddress((void**)&hnB,   g_hnB);
    cudaGetSymbolAddress((void**)&normv, g_norm);
    cudaGetSymbolAddress((void**)&denom, g_denom);

    const int TB = 256;
    const int n_agg4 = n * 32 / 4;
    const int n_den4 = n / 4;
    const int npairs = (ne + 1) / 2;
    dim3 gN((n + TB - 1) / TB);
    dim3 gN8(((size_t)n * 8 + TB - 1) / TB);
    dim3 gP8(((size_t)npairs * 8 + TB - 1) / TB);
    dim3 gZ((n_agg4 + TB - 1) / TB);

    // K1: hn0/norm0
    k_gemm1<<<gN, TB>>>(feat, w1, b1, hnA, normv, n);

    // ---- layer 0 ----
    k_zero_layer<<<gZ, TB>>>((float4*)agg, (float4*)denom, n_agg4, n_den4);
    k_edge_fused<<<gP8, TB>>>(src, dst, hnA, normv, betas, 0, denom, agg, ne);
    k_norm_mid<<<gN8, TB>>>(agg, denom, hnB, normv, n);

    // ---- layer 1 ----
    k_zero_layer<<<gZ, TB>>>((float4*)agg, (float4*)denom, n_agg4, n_den4);
    k_edge_fused<<<gP8, TB>>>(src, dst, hnB, normv, betas, 1, denom, agg, ne);

    // Head (divide + relu fused)
    k_final<<<(n + 127) / 128, 128>>>(agg, denom, w2, b2, out, n);
}